// round 16
// baseline (speedup 1.0000x reference)
#include <cuda_runtime.h>
#include <cuda_fp16.h>
#include <cstdint>
#include <mma.h>
using namespace nvcuda;

#define NTOK 4096
#define DDIM 1024
#define EEXP 8
#define HDIM 4096
#define NPAIR (NTOK*2)

#define BM 128
#define BN 256
#define BK 64
#define LDA 72
#define LDB 264
#define ASTAGE (BM*LDA)
#define BSTAGE (BK*LDB)
#define STAGE_H (ASTAGE + BSTAGE)
#define NSTAGE 4
#define SMEM_BYTES (NSTAGE*STAGE_H*2)      // 208896 B
#define LDC 264
#define NB1 (HDIM/BN)                      // 16

// ---------------- device scratch ----------------
__device__ __half g_xa [(size_t)NPAIR*DDIM];
__device__ __half g_h  [(size_t)NPAIR*HDIM];
__device__ __half g_w1h[(size_t)EEXP*DDIM*HDIM];
__device__ __half g_w2h[(size_t)EEXP*HDIM*DDIM];
__device__ int    g_counts[EEXP];
__device__ int    g_tilec[2];
__device__ int    g_c1done[NB1];           // per-N-panel w1 conversion counters (128 arrivals)
__device__ int    g_tok[EEXP*NTOK];
__device__ float  g_wt [EEXP*NTOK];
__device__ int    g_ftok[NPAIR];
__device__ float  g_fwt [NPAIR];

__device__ __forceinline__ void cpa16(void* dst, const void* src){
    uint32_t d = (uint32_t)__cvta_generic_to_shared(dst);
    asm volatile("cp.async.cg.shared.global [%0], [%1], 16;\n" :: "r"(d), "l"(src));
}
__device__ __forceinline__ void cp_commit(){ asm volatile("cp.async.commit_group;\n"); }
template<int N> __device__ __forceinline__ void cp_wait(){
    asm volatile("cp.async.wait_group %0;\n" :: "n"(N));
}
__device__ __forceinline__ int ld_acq(const int* p){
    int v;
    asm volatile("ld.acquire.gpu.global.b32 %0, [%1];" : "=r"(v) : "l"(p) : "memory");
    return v;
}

__device__ __forceinline__ float gelu_tanh(float v){
    const float c = 0.7978845608028654f;
    float t = tanhf(c*(v + 0.044715f*v*v*v));
    return 0.5f*v*(1.0f+t);
}

// ---------------- init ----------------
__global__ void init_kernel(){
    int t = threadIdx.x;
    if (t < EEXP) g_counts[t] = 0;
    if (t < NB1) g_c1done[t] = 0;
    if (t < 2) g_tilec[t] = 0;
}

// Router: Wg^T staged in smem, one warp per token.
__global__ void router_kernel(const float* __restrict__ x, const float* __restrict__ Wg,
                              const float* __restrict__ bg, float* __restrict__ logits_out,
                              int write_logits){
    __shared__ float sWgT[EEXP*DDIM];   // [e][d], 32KB
    const int tid = threadIdx.x;
    for (int i = tid; i < EEXP*DDIM; i += blockDim.x){
        int d = i >> 3, e = i & 7;
        sWgT[e*DDIM + d] = Wg[i];
    }
    __syncthreads();

    const int warp = tid >> 5;
    const int lane = tid & 31;
    const int n = blockIdx.x * 8 + warp;
    if (n >= NTOK) return;
    const float* xr = x + (size_t)n * DDIM;

    float l[EEXP];
    #pragma unroll
    for (int e = 0; e < EEXP; e++) l[e] = 0.f;
    #pragma unroll 4
    for (int d = lane; d < DDIM; d += 32){
        float xs = xr[d];
        #pragma unroll
        for (int e = 0; e < EEXP; e++)
            l[e] += xs * sWgT[e*DDIM + d];
    }
    #pragma unroll
    for (int off = 16; off > 0; off >>= 1){
        #pragma unroll
        for (int e = 0; e < EEXP; e++)
            l[e] += __shfl_xor_sync(0xffffffff, l[e], off);
    }
    if (lane == 0){
        #pragma unroll
        for (int e = 0; e < EEXP; e++) l[e] += bg[e];
        if (write_logits){
            #pragma unroll
            for (int e = 0; e < EEXP; e++) logits_out[(size_t)n*EEXP + e] = l[e];
        }
        int e0 = 0;
        #pragma unroll
        for (int e = 1; e < EEXP; e++) if (l[e] > l[e0]) e0 = e;
        int e1 = (e0 == 0) ? 1 : 0;
        #pragma unroll
        for (int e = 0; e < EEXP; e++) if (e != e0 && l[e] > l[e1]) e1 = e;
        float a = l[e0], b = l[e1];
        float ex = expf(b - a);
        float s  = 1.0f / (1.0f + ex);
        float w0 = s, w1 = ex * s;
        int p0 = atomicAdd(&g_counts[e0], 1);
        g_tok[e0*NTOK + p0] = n; g_wt[e0*NTOK + p0] = w0;
        int p1 = atomicAdd(&g_counts[e1], 1);
        g_tok[e1*NTOK + p1] = n; g_wt[e1*NTOK + p1] = w1;
    }
}

// ---------------- prep ----------------
// w1 conversion in N-panel order: panel nb ready once g_c1done[nb] == 128.
__global__ void conv_w1_panels(const float* __restrict__ in, __half* __restrict__ out){
    const int b = blockIdx.x;          // 0..127 -> rows [b*64, b*64+64)
    const int tid = threadIdx.x;
    const int lane8 = (tid & 31) * 8;
    const int rstep = tid >> 5;
    #pragma unroll 1
    for (int nb = 0; nb < NB1; nb++){
        const int colBase = nb * 256;
        #pragma unroll
        for (int rr = rstep; rr < 64; rr += 8){
            const int grow = b*64 + rr;
            const float* sp = in + (size_t)grow*HDIM + colBase + lane8;
            float4 v0 = *(const float4*)sp;
            float4 v1 = *(const float4*)(sp + 4);
            __half2 h0 = __floats2half2_rn(v0.x, v0.y);
            __half2 h1 = __floats2half2_rn(v0.z, v0.w);
            __half2 h2 = __floats2half2_rn(v1.x, v1.y);
            __half2 h3 = __floats2half2_rn(v1.z, v1.w);
            *(uint4*)(out + (size_t)grow*HDIM + colBase + lane8) =
                make_uint4(*(uint32_t*)&h0, *(uint32_t*)&h1,
                           *(uint32_t*)&h2, *(uint32_t*)&h3);
        }
        __threadfence();
        __syncthreads();
        if (tid == 0) atomicAdd(&g_c1done[nb], 1);
    }
}

__global__ void conv_f2h(const float* __restrict__ in, __half* __restrict__ out, size_t n){
    size_t i = ((size_t)blockIdx.x * blockDim.x + threadIdx.x) * 8;
    if (i >= n) return;
    float4 v0 = *(const float4*)(in + i);
    float4 v1 = *(const float4*)(in + i + 4);
    __half2 h0 = __floats2half2_rn(v0.x, v0.y);
    __half2 h1 = __floats2half2_rn(v0.z, v0.w);
    __half2 h2 = __floats2half2_rn(v1.x, v1.y);
    __half2 h3 = __floats2half2_rn(v1.z, v1.w);
    uint4 pk = make_uint4(*(uint32_t*)&h0, *(uint32_t*)&h1, *(uint32_t*)&h2, *(uint32_t*)&h3);
    *(uint4*)(out + i) = pk;
}

// gather: computes expert offsets locally from g_counts.
__global__ void gather_kernel(const float* __restrict__ x){
    int p = blockIdx.x;
    int offs[EEXP];
    {
        int s = 0;
        #pragma unroll
        for (int e = 0; e < EEXP; e++){ offs[e] = s; s += g_counts[e]; }
    }
    int e = 0;
    #pragma unroll
    for (int k = 1; k < EEXP; k++) if (p >= offs[k]) e = k;
    int i = p - offs[e];
    int tok = g_tok[e*NTOK + i];
    float wt = g_wt[e*NTOK + i];
    if (threadIdx.x == 0){ g_ftok[p] = tok; g_fwt[p] = wt; }
    const float4* src = (const float4*)(x + (size_t)tok*DDIM);
    __half2* dst = (__half2*)(g_xa + (size_t)p*DDIM);
    for (int j = threadIdx.x; j < DDIM/4; j += blockDim.x){
        float4 v = src[j];
        dst[2*j]     = __floats2half2_rn(v.x, v.y);
        dst[2*j + 1] = __floats2half2_rn(v.z, v.w);
    }
}

// ---------------- persistent fp16 wmma GEMM: cross-tile pipelined ----------------
// nb-outer tile order (B-panel L2 sharing). Next tile's stages 0,1 are issued into
// buffers 0,1 BEFORE the epilogue, which stages C in buffers 2,3 (= last-consumed
// stage buffers since KSTEPS % 4 == 0). MODE 2 atomically scatters into out.
template<int KDIM, int NDIM, int MODE>
__global__ void __launch_bounds__(256, 1)
moe_gemm(const __half* __restrict__ Amat, const __half* __restrict__ Bw,
         const float* __restrict__ bias, float* __restrict__ out){
    const int tid = threadIdx.x;
    const int warpId = tid >> 5;
    const int wr = warpId & 1;
    const int wc = warpId >> 1;
    constexpr int NB = NDIM / BN;
    constexpr int KSTEPS = KDIM / BK;
    static_assert(KSTEPS % 4 == 0, "Cs overlays buffers 2,3");

    extern __shared__ char smem_raw[];
    __shared__ int sTile;

    // local prefix over experts
    int cnts[EEXP], offs[EEXP], mbp[EEXP+1];
    {
        int s = 0, mb = 0;
        mbp[0] = 0;
        #pragma unroll
        for (int e = 0; e < EEXP; e++){
            cnts[e] = g_counts[e];
            offs[e] = s; s += cnts[e];
            mb += (cnts[e] + BM - 1) / BM;
            mbp[e+1] = mb;
        }
    }
    const int mbTotal = mbp[EEXP];
    const int totalTiles = mbTotal * NB;

    using FragA = wmma::fragment<wmma::matrix_a, 16,16,16, __half, wmma::row_major>;
    using FragB = wmma::fragment<wmma::matrix_b, 16,16,16, __half, wmma::row_major>;
    using FragC = wmma::fragment<wmma::accumulator, 16,16,16, float>;

    int e=0, count=0, off=0, mBase=0, n0=0;
    const __half* asrc[4]; int adoff[4];
    const __half* bsrc[8]; int bdoff[8];

    auto decode_setup = [&](int tt){
        const int nb = tt / mbTotal;
        const int gmb = tt - nb * mbTotal;
        e = 0;
        #pragma unroll
        for (int k = 1; k < EEXP; k++) if (gmb >= mbp[k]) e = k;
        count = cnts[e];
        off = offs[e];
        mBase = (gmb - mbp[e]) * BM;
        n0 = nb * BN;
        if (MODE == 1){
            if (tid == 0){
                while (ld_acq(&g_c1done[nb]) < 128) __nanosleep(64);
            }
            __syncthreads();
        }
        #pragma unroll
        for (int v = 0; v < 4; v++){
            int i = tid + v*256;
            int row = i >> 3, ch = i & 7;
            int m = mBase + row; if (m > count - 1) m = count - 1;
            asrc[v] = Amat + (size_t)(off + m)*KDIM + ch*8;
            adoff[v] = row*LDA + ch*8;
        }
        const __half* Wb = Bw + (size_t)e*KDIM*NDIM + n0;
        #pragma unroll
        for (int v = 0; v < 8; v++){
            int i = tid + v*256;
            int row = i >> 5, ch = i & 31;
            bsrc[v] = Wb + (size_t)row*NDIM + ch*8;
            bdoff[v] = row*LDB + ch*8;
        }
    };

    auto issue_stage = [&](int s){
        if (s < KSTEPS){
            __half* Ab = (__half*)smem_raw + (s % NSTAGE)*STAGE_H;
            __half* Bb = Ab + ASTAGE;
            size_t ka = (size_t)s * BK;
            #pragma unroll
            for (int v = 0; v < 4; v++) cpa16(Ab + adoff[v], asrc[v] + ka);
            #pragma unroll
            for (int v = 0; v < 8; v++) cpa16(Bb + bdoff[v], bsrc[v] + (size_t)ka*NDIM);
        }
        cp_commit();
    };

    // fetch first tile
    if (tid == 0) sTile = atomicAdd(&g_tilec[MODE-1], 1);
    __syncthreads();
    int t = sTile;
    if (t >= totalTiles) return;
    decode_setup(t);
    issue_stage(0); issue_stage(1);

    while (true){
        issue_stage(2);

        FragC acc[4][4];
        #pragma unroll
        for (int i = 0; i < 4; i++)
            #pragma unroll
            for (int j = 0; j < 4; j++) wmma::fill_fragment(acc[i][j], 0.0f);

        #pragma unroll 1
        for (int kt = 0; kt < KSTEPS; kt++){
            cp_wait<2>();
            __syncthreads();
            issue_stage(kt + 3);

            const __half* As = (__half*)smem_raw + (kt % NSTAGE)*STAGE_H;
            const __half* Bs = As + ASTAGE;
            #pragma unroll
            for (int kk = 0; kk < BK; kk += 16){
                FragA a[4];
                #pragma unroll
                for (int i = 0; i < 4; i++)
                    wmma::load_matrix_sync(a[i], As + (wr*64 + i*16)*LDA + kk, LDA);
                #pragma unroll
                for (int j = 0; j < 4; j++){
                    FragB b;
                    wmma::load_matrix_sync(b, Bs + kk*LDB + wc*64 + j*16, LDB);
                    #pragma unroll
                    for (int i = 0; i < 4; i++)
                        wmma::mma_sync(acc[i][j], a[i], b, acc[i][j]);
                }
            }
        }
        __syncthreads();   // all warps done with all stage buffers

        // save current-tile epilogue scalars
        const int curOff = off, curMBase = mBase, curN0 = n0, curCount = count;
        const float* be = bias + (size_t)e*NDIM + curN0;

        // fetch next tile; prefetch its stages 0,1 into buffers 0,1 (free now)
        if (tid == 0) sTile = atomicAdd(&g_tilec[MODE-1], 1);
        __syncthreads();
        t = sTile;
        const bool more = (t < totalTiles);
        if (more){
            decode_setup(t);
            issue_stage(0); issue_stage(1);
        }

        // epilogue: Cs overlays buffers 2,3 (104KB available, need 67.6KB)
        float* Cs = (float*)((__half*)smem_raw + 2*STAGE_H);
        #pragma unroll 1
        for (int hf = 0; hf < 2; hf++){
            if (wr == hf){
                #pragma unroll
                for (int i = 0; i < 4; i++)
                    #pragma unroll
                    for (int j = 0; j < 4; j++)
                        wmma::store_matrix_sync(Cs + (i*16)*LDC + wc*64 + j*16,
                                                acc[i][j], LDC, wmma::mem_row_major);
            }
            __syncthreads();
            #pragma unroll 1
            for (int it = 0; it < 16; it++){
                int idx4 = tid + it*256;
                int row = idx4 >> 6;
                int c4  = (idx4 & 63) * 4;
                int gr = curMBase + hf*64 + row;
                if (gr < curCount){
                    float4 v  = *(const float4*)(Cs + row*LDC + c4);
                    float4 bb = *(const float4*)(be + c4);
                    if (MODE == 1){
                        float o0 = gelu_tanh(v.x + bb.x);
                        float o1 = gelu_tanh(v.y + bb.y);
                        float o2 = gelu_tanh(v.z + bb.z);
                        float o3 = gelu_tanh(v.w + bb.w);
                        __half2 h0 = __floats2half2_rn(o0, o1);
                        __half2 h1 = __floats2half2_rn(o2, o3);
                        uint2 pk = make_uint2(*(uint32_t*)&h0, *(uint32_t*)&h1);
                        *(uint2*)(g_h + (size_t)(curOff+gr)*HDIM + curN0 + c4) = pk;
                    } else {
                        int tok = g_ftok[curOff+gr];
                        float wgt = g_fwt[curOff+gr];
                        float* op = out + (size_t)tok*DDIM + curN0 + c4;
                        atomicAdd(op + 0, wgt*(v.x + bb.x));
                        atomicAdd(op + 1, wgt*(v.y + bb.y));
                        atomicAdd(op + 2, wgt*(v.z + bb.z));
                        atomicAdd(op + 3, wgt*(v.w + bb.w));
                    }
                }
            }
            __syncthreads();
        }
        if (!more) break;
    }
}

// ---------------- launch ----------------
extern "C" void kernel_launch(void* const* d_in, const int* in_sizes, int n_in,
                              void* d_out, int out_size){
    const float* x  = (const float*)d_in[0];
    const float* Wg = (const float*)d_in[1];
    const float* bg = (const float*)d_in[2];
    const float* w1 = (const float*)d_in[3];
    const float* b1 = (const float*)d_in[4];
    const float* w2 = (const float*)d_in[5];
    const float* b2 = (const float*)d_in[6];
    float* out = (float*)d_out;

    cudaFuncSetAttribute(moe_gemm<DDIM, HDIM, 1>,
                         cudaFuncAttributeMaxDynamicSharedMemorySize, SMEM_BYTES);
    cudaFuncSetAttribute(moe_gemm<HDIM, DDIM, 2>,
                         cudaFuncAttributeMaxDynamicSharedMemorySize, SMEM_BYTES);

    int dev = 0, nsm = 148;
    cudaGetDevice(&dev);
    cudaDeviceGetAttribute(&nsm, cudaDevAttrMultiProcessorCount, dev);

    __half* w1h; cudaGetSymbolAddress((void**)&w1h, g_w1h);
    __half* w2h; cudaGetSymbolAddress((void**)&w2h, g_w2h);
    __half* xa;  cudaGetSymbolAddress((void**)&xa,  g_xa);
    __half* hbuf;cudaGetSymbolAddress((void**)&hbuf,g_h);

    cudaStream_t s1;
    cudaStreamCreateWithFlags(&s1, cudaStreamNonBlocking);
    cudaEvent_t evR, evW2;
    cudaEventCreateWithFlags(&evR,  cudaEventDisableTiming);
    cudaEventCreateWithFlags(&evW2, cudaEventDisableTiming);

    const size_t WN = (size_t)EEXP*DDIM*HDIM;
    int write_logits = (out_size >= NTOK*DDIM + NTOK*EEXP) ? 1 : 0;

    // main stream: zero out, init counters, router (uncontended — convs fork after)
    cudaMemsetAsync(out, 0, (size_t)NTOK*DDIM*sizeof(float));
    init_kernel<<<1, 128>>>();
    router_kernel<<<NTOK/8, 256>>>(x, Wg, bg, out + (size_t)NTOK*DDIM, write_logits);
    cudaEventRecord(evR, 0);

    // side stream: forked after router; w1 panels (GEMM1 gates per-panel), then w2
    cudaStreamWaitEvent(s1, evR, 0);
    conv_w1_panels<<<128, 256, 0, s1>>>(w1, w1h);
    conv_f2h<<<(int)(WN/8/256), 256, 0, s1>>>(w2, w2h, WN);
    cudaEventRecord(evW2, s1);

    // main stream: gather (computes offsets locally), then GEMMs
    gather_kernel<<<NPAIR, 128>>>(x);

    moe_gemm<DDIM, HDIM, 1><<<nsm, 256, SMEM_BYTES>>>(xa, w1h, b1, out);
    cudaStreamWaitEvent(0, evW2, 0);
    moe_gemm<HDIM, DDIM, 2><<<nsm, 256, SMEM_BYTES>>>(hbuf, w2h, b2, out);
}

// round 17
// speedup vs baseline: 1.0292x; 1.0292x over previous
#include <cuda_runtime.h>
#include <cuda_fp16.h>
#include <cstdint>
#include <mma.h>
using namespace nvcuda;

#define NTOK 4096
#define DDIM 1024
#define EEXP 8
#define HDIM 4096
#define NPAIR (NTOK*2)

#define BM 128
#define BN 256
#define BK 64
#define LDA 72
#define LDB 264
#define ASTAGE (BM*LDA)
#define BSTAGE (BK*LDB)
#define STAGE_H (ASTAGE + BSTAGE)
#define NSTAGE 4
#define SMEM_BYTES (NSTAGE*STAGE_H*2)      // 208896 B
#define LDC 264
#define NB1 (HDIM/BN)                      // 16

// ---------------- device scratch ----------------
__device__ __half g_xa [(size_t)NPAIR*DDIM];
__device__ __half g_h  [(size_t)NPAIR*HDIM];
__device__ __half g_w1h[(size_t)EEXP*DDIM*HDIM];
__device__ __half g_w2h[(size_t)EEXP*HDIM*DDIM];
__device__ int    g_counts[EEXP];
__device__ int    g_tilec[2];
__device__ int    g_c1done[NB1];           // per-N-panel w1 conversion counters (128 arrivals)
__device__ int    g_tok[EEXP*NTOK];
__device__ float  g_wt [EEXP*NTOK];
__device__ int    g_ftok[NPAIR];
__device__ float  g_fwt [NPAIR];

__device__ __forceinline__ void cpa16(void* dst, const void* src){
    uint32_t d = (uint32_t)__cvta_generic_to_shared(dst);
    asm volatile("cp.async.cg.shared.global [%0], [%1], 16;\n" :: "r"(d), "l"(src));
}
__device__ __forceinline__ void cp_commit(){ asm volatile("cp.async.commit_group;\n"); }
template<int N> __device__ __forceinline__ void cp_wait(){
    asm volatile("cp.async.wait_group %0;\n" :: "n"(N));
}
__device__ __forceinline__ int ld_acq(const int* p){
    int v;
    asm volatile("ld.acquire.gpu.global.b32 %0, [%1];" : "=r"(v) : "l"(p) : "memory");
    return v;
}

__device__ __forceinline__ float gelu_tanh(float v){
    const float c = 0.7978845608028654f;
    float t = tanhf(c*(v + 0.044715f*v*v*v));
    return 0.5f*v*(1.0f+t);
}

// ---------------- init ----------------
__global__ void init_kernel(){
    int t = threadIdx.x;
    if (t < EEXP) g_counts[t] = 0;
    if (t < NB1) g_c1done[t] = 0;
    if (t < 2) g_tilec[t] = 0;
}

// Router: Wg^T staged in smem, one warp per token.
__global__ void router_kernel(const float* __restrict__ x, const float* __restrict__ Wg,
                              const float* __restrict__ bg, float* __restrict__ logits_out,
                              int write_logits){
    __shared__ float sWgT[EEXP*DDIM];   // [e][d], 32KB
    const int tid = threadIdx.x;
    for (int i = tid; i < EEXP*DDIM; i += blockDim.x){
        int d = i >> 3, e = i & 7;
        sWgT[e*DDIM + d] = Wg[i];
    }
    __syncthreads();

    const int warp = tid >> 5;
    const int lane = tid & 31;
    const int n = blockIdx.x * 8 + warp;
    if (n >= NTOK) return;
    const float* xr = x + (size_t)n * DDIM;

    float l[EEXP];
    #pragma unroll
    for (int e = 0; e < EEXP; e++) l[e] = 0.f;
    #pragma unroll 4
    for (int d = lane; d < DDIM; d += 32){
        float xs = xr[d];
        #pragma unroll
        for (int e = 0; e < EEXP; e++)
            l[e] += xs * sWgT[e*DDIM + d];
    }
    #pragma unroll
    for (int off = 16; off > 0; off >>= 1){
        #pragma unroll
        for (int e = 0; e < EEXP; e++)
            l[e] += __shfl_xor_sync(0xffffffff, l[e], off);
    }
    if (lane == 0){
        #pragma unroll
        for (int e = 0; e < EEXP; e++) l[e] += bg[e];
        if (write_logits){
            #pragma unroll
            for (int e = 0; e < EEXP; e++) logits_out[(size_t)n*EEXP + e] = l[e];
        }
        int e0 = 0;
        #pragma unroll
        for (int e = 1; e < EEXP; e++) if (l[e] > l[e0]) e0 = e;
        int e1 = (e0 == 0) ? 1 : 0;
        #pragma unroll
        for (int e = 0; e < EEXP; e++) if (e != e0 && l[e] > l[e1]) e1 = e;
        float a = l[e0], b = l[e1];
        float ex = expf(b - a);
        float s  = 1.0f / (1.0f + ex);
        float w0 = s, w1 = ex * s;
        int p0 = atomicAdd(&g_counts[e0], 1);
        g_tok[e0*NTOK + p0] = n; g_wt[e0*NTOK + p0] = w0;
        int p1 = atomicAdd(&g_counts[e1], 1);
        g_tok[e1*NTOK + p1] = n; g_wt[e1*NTOK + p1] = w1;
    }
}

// ---------------- prep ----------------
// w1 conversion in N-panel order: panel nb ready once g_c1done[nb] == 128.
__global__ void conv_w1_panels(const float* __restrict__ in, __half* __restrict__ out){
    const int b = blockIdx.x;          // 0..127 -> rows [b*64, b*64+64)
    const int tid = threadIdx.x;
    const int lane8 = (tid & 31) * 8;
    const int rstep = tid >> 5;
    #pragma unroll 1
    for (int nb = 0; nb < NB1; nb++){
        const int colBase = nb * 256;
        #pragma unroll
        for (int rr = rstep; rr < 64; rr += 8){
            const int grow = b*64 + rr;
            const float* sp = in + (size_t)grow*HDIM + colBase + lane8;
            float4 v0 = *(const float4*)sp;
            float4 v1 = *(const float4*)(sp + 4);
            __half2 h0 = __floats2half2_rn(v0.x, v0.y);
            __half2 h1 = __floats2half2_rn(v0.z, v0.w);
            __half2 h2 = __floats2half2_rn(v1.x, v1.y);
            __half2 h3 = __floats2half2_rn(v1.z, v1.w);
            *(uint4*)(out + (size_t)grow*HDIM + colBase + lane8) =
                make_uint4(*(uint32_t*)&h0, *(uint32_t*)&h1,
                           *(uint32_t*)&h2, *(uint32_t*)&h3);
        }
        __threadfence();
        __syncthreads();
        if (tid == 0) atomicAdd(&g_c1done[nb], 1);
    }
}

__global__ void conv_f2h(const float* __restrict__ in, __half* __restrict__ out, size_t n){
    size_t i = ((size_t)blockIdx.x * blockDim.x + threadIdx.x) * 8;
    if (i >= n) return;
    float4 v0 = *(const float4*)(in + i);
    float4 v1 = *(const float4*)(in + i + 4);
    __half2 h0 = __floats2half2_rn(v0.x, v0.y);
    __half2 h1 = __floats2half2_rn(v0.z, v0.w);
    __half2 h2 = __floats2half2_rn(v1.x, v1.y);
    __half2 h3 = __floats2half2_rn(v1.z, v1.w);
    uint4 pk = make_uint4(*(uint32_t*)&h0, *(uint32_t*)&h1, *(uint32_t*)&h2, *(uint32_t*)&h3);
    *(uint4*)(out + i) = pk;
}

// gather: computes expert offsets locally from g_counts.
__global__ void gather_kernel(const float* __restrict__ x){
    int p = blockIdx.x;
    int offs[EEXP];
    {
        int s = 0;
        #pragma unroll
        for (int e = 0; e < EEXP; e++){ offs[e] = s; s += g_counts[e]; }
    }
    int e = 0;
    #pragma unroll
    for (int k = 1; k < EEXP; k++) if (p >= offs[k]) e = k;
    int i = p - offs[e];
    int tok = g_tok[e*NTOK + i];
    float wt = g_wt[e*NTOK + i];
    if (threadIdx.x == 0){ g_ftok[p] = tok; g_fwt[p] = wt; }
    const float4* src = (const float4*)(x + (size_t)tok*DDIM);
    __half2* dst = (__half2*)(g_xa + (size_t)p*DDIM);
    for (int j = threadIdx.x; j < DDIM/4; j += blockDim.x){
        float4 v = src[j];
        dst[2*j]     = __floats2half2_rn(v.x, v.y);
        dst[2*j + 1] = __floats2half2_rn(v.z, v.w);
    }
}

// ---------------- persistent fp16 wmma GEMM: tile stealing, 4-stage pipeline ----------------
// Tile order M-fastest: nb = t / mbTotal (outer) -> concurrent CTAs share B panels in L2.
// MODE 1 gates each tile on its w1 N-panel conversion counter.
// Single-pass epilogue: full 128x264 fp32 C tile staged in (drained) pipeline smem.
template<int KDIM, int NDIM, int MODE>
__global__ void __launch_bounds__(256, 1)
moe_gemm(const __half* __restrict__ Amat, const __half* __restrict__ Bw,
         const float* __restrict__ bias, float* __restrict__ out){
    const int tid = threadIdx.x;
    const int warpId = tid >> 5;
    const int wr = warpId & 1;
    const int wc = warpId >> 1;
    constexpr int NB = NDIM / BN;
    constexpr int KSTEPS = KDIM / BK;
    static_assert(BM*LDC*4 <= SMEM_BYTES, "full C tile fits drained pipeline smem");

    extern __shared__ char smem_raw[];
    __shared__ int sTile;

    // local prefix over experts
    int cnts[EEXP], offs[EEXP], mbp[EEXP+1];
    {
        int s = 0, mb = 0;
        mbp[0] = 0;
        #pragma unroll
        for (int e = 0; e < EEXP; e++){
            cnts[e] = g_counts[e];
            offs[e] = s; s += cnts[e];
            mb += (cnts[e] + BM - 1) / BM;
            mbp[e+1] = mb;
        }
    }
    const int mbTotal = mbp[EEXP];
    const int totalTiles = mbTotal * NB;

    using FragA = wmma::fragment<wmma::matrix_a, 16,16,16, __half, wmma::row_major>;
    using FragB = wmma::fragment<wmma::matrix_b, 16,16,16, __half, wmma::row_major>;
    using FragC = wmma::fragment<wmma::accumulator, 16,16,16, float>;

    while (true){
        if (tid == 0) sTile = atomicAdd(&g_tilec[MODE-1], 1);
        __syncthreads();
        const int t = sTile;
        __syncthreads();
        if (t >= totalTiles) break;

        const int nb = t / mbTotal;
        const int gmb = t - nb * mbTotal;
        int e = 0;
        #pragma unroll
        for (int k = 1; k < EEXP; k++) if (gmb >= mbp[k]) e = k;
        const int mb = gmb - mbp[e];
        const int count = cnts[e];
        const int off = offs[e];
        const int mBase = mb * BM;
        const int n0 = nb * BN;

        if (MODE == 1){
            if (tid == 0){
                while (ld_acq(&g_c1done[nb]) < 128) __nanosleep(64);
            }
            __syncthreads();
        }

        const __half* asrc[4];
        int adoff[4];
        #pragma unroll
        for (int v = 0; v < 4; v++){
            int i = tid + v*256;
            int row = i >> 3, ch = i & 7;
            int m = mBase + row; if (m > count - 1) m = count - 1;
            asrc[v] = Amat + (size_t)(off + m)*KDIM + ch*8;
            adoff[v] = row*LDA + ch*8;
        }
        const __half* bsrc[8];
        int bdoff[8];
        const __half* Wb = Bw + (size_t)e*KDIM*NDIM + n0;
        #pragma unroll
        for (int v = 0; v < 8; v++){
            int i = tid + v*256;
            int row = i >> 5, ch = i & 31;
            bsrc[v] = Wb + (size_t)row*NDIM + ch*8;
            bdoff[v] = row*LDB + ch*8;
        }

        auto issue_stage = [&](int s){
            if (s < KSTEPS){
                __half* Ab = (__half*)smem_raw + (s % NSTAGE)*STAGE_H;
                __half* Bb = Ab + ASTAGE;
                size_t ka = (size_t)s * BK;
                #pragma unroll
                for (int v = 0; v < 4; v++) cpa16(Ab + adoff[v], asrc[v] + ka);
                #pragma unroll
                for (int v = 0; v < 8; v++) cpa16(Bb + bdoff[v], bsrc[v] + (size_t)ka*NDIM);
            }
            cp_commit();
        };

        issue_stage(0); issue_stage(1); issue_stage(2);

        FragC acc[4][4];
        #pragma unroll
        for (int i = 0; i < 4; i++)
            #pragma unroll
            for (int j = 0; j < 4; j++) wmma::fill_fragment(acc[i][j], 0.0f);

        #pragma unroll 1
        for (int kt = 0; kt < KSTEPS; kt++){
            cp_wait<2>();
            __syncthreads();
            issue_stage(kt + 3);

            const __half* As = (__half*)smem_raw + (kt % NSTAGE)*STAGE_H;
            const __half* Bs = As + ASTAGE;
            #pragma unroll
            for (int kk = 0; kk < BK; kk += 16){
                FragA a[4];
                #pragma unroll
                for (int i = 0; i < 4; i++)
                    wmma::load_matrix_sync(a[i], As + (wr*64 + i*16)*LDA + kk, LDA);
                #pragma unroll
                for (int j = 0; j < 4; j++){
                    FragB b;
                    wmma::load_matrix_sync(b, Bs + kk*LDB + wc*64 + j*16, LDB);
                    #pragma unroll
                    for (int i = 0; i < 4; i++)
                        wmma::mma_sync(acc[i][j], a[i], b, acc[i][j]);
                }
            }
        }
        cp_wait<0>();
        __syncthreads();   // pipeline fully drained; entire smem is free

        // ---- single-pass epilogue: full 128x264 fp32 C tile (135.2KB <= 204KB) ----
        float* Cs = (float*)smem_raw;
        #pragma unroll
        for (int i = 0; i < 4; i++)
            #pragma unroll
            for (int j = 0; j < 4; j++)
                wmma::store_matrix_sync(Cs + (wr*64 + i*16)*LDC + wc*64 + j*16,
                                        acc[i][j], LDC, wmma::mem_row_major);
        __syncthreads();

        const float* be = bias + (size_t)e*NDIM + n0;
        #pragma unroll 1
        for (int it = 0; it < 32; it++){
            int idx4 = tid + it*256;
            int row = idx4 >> 6;
            int c4  = (idx4 & 63) * 4;
            int gr = mBase + row;
            if (gr < count){
                float4 v  = *(const float4*)(Cs + row*LDC + c4);
                float4 bb = *(const float4*)(be + c4);
                if (MODE == 1){
                    float o0 = gelu_tanh(v.x + bb.x);
                    float o1 = gelu_tanh(v.y + bb.y);
                    float o2 = gelu_tanh(v.z + bb.z);
                    float o3 = gelu_tanh(v.w + bb.w);
                    __half2 h0 = __floats2half2_rn(o0, o1);
                    __half2 h1 = __floats2half2_rn(o2, o3);
                    uint2 pk = make_uint2(*(uint32_t*)&h0, *(uint32_t*)&h1);
                    *(uint2*)(g_h + (size_t)(off+gr)*HDIM + n0 + c4) = pk;
                } else {
                    int tok = g_ftok[off+gr];
                    float wgt = g_fwt[off+gr];
                    float* op = out + (size_t)tok*DDIM + n0 + c4;
                    atomicAdd(op + 0, wgt*(v.x + bb.x));
                    atomicAdd(op + 1, wgt*(v.y + bb.y));
                    atomicAdd(op + 2, wgt*(v.z + bb.z));
                    atomicAdd(op + 3, wgt*(v.w + bb.w));
                }
            }
        }
        __syncthreads();
    }
}

// ---------------- launch ----------------
extern "C" void kernel_launch(void* const* d_in, const int* in_sizes, int n_in,
                              void* d_out, int out_size){
    const float* x  = (const float*)d_in[0];
    const float* Wg = (const float*)d_in[1];
    const float* bg = (const float*)d_in[2];
    const float* w1 = (const float*)d_in[3];
    const float* b1 = (const float*)d_in[4];
    const float* w2 = (const float*)d_in[5];
    const float* b2 = (const float*)d_in[6];
    float* out = (float*)d_out;

    cudaFuncSetAttribute(moe_gemm<DDIM, HDIM, 1>,
                         cudaFuncAttributeMaxDynamicSharedMemorySize, SMEM_BYTES);
    cudaFuncSetAttribute(moe_gemm<HDIM, DDIM, 2>,
                         cudaFuncAttributeMaxDynamicSharedMemorySize, SMEM_BYTES);

    int dev = 0, nsm = 148;
    cudaGetDevice(&dev);
    cudaDeviceGetAttribute(&nsm, cudaDevAttrMultiProcessorCount, dev);

    __half* w1h; cudaGetSymbolAddress((void**)&w1h, g_w1h);
    __half* w2h; cudaGetSymbolAddress((void**)&w2h, g_w2h);
    __half* xa;  cudaGetSymbolAddress((void**)&xa,  g_xa);
    __half* hbuf;cudaGetSymbolAddress((void**)&hbuf,g_h);

    cudaStream_t s1;
    cudaStreamCreateWithFlags(&s1, cudaStreamNonBlocking);
    cudaEvent_t evR, evW2;
    cudaEventCreateWithFlags(&evR,  cudaEventDisableTiming);
    cudaEventCreateWithFlags(&evW2, cudaEventDisableTiming);

    const size_t WN = (size_t)EEXP*DDIM*HDIM;
    int write_logits = (out_size >= NTOK*DDIM + NTOK*EEXP) ? 1 : 0;

    // main stream: zero out, init counters, router (uncontended — convs fork after)
    cudaMemsetAsync(out, 0, (size_t)NTOK*DDIM*sizeof(float));
    init_kernel<<<1, 128>>>();
    router_kernel<<<NTOK/8, 256>>>(x, Wg, bg, out + (size_t)NTOK*DDIM, write_logits);
    cudaEventRecord(evR, 0);

    // side stream: forked after router; w1 panels (GEMM1 gates per-panel), then w2
    cudaStreamWaitEvent(s1, evR, 0);
    conv_w1_panels<<<128, 256, 0, s1>>>(w1, w1h);
    conv_f2h<<<(int)(WN/8/256), 256, 0, s1>>>(w2, w2h, WN);
    cudaEventRecord(evW2, s1);

    // main stream: gather (computes offsets locally), then GEMMs
    gather_kernel<<<NPAIR, 128>>>(x);

    moe_gemm<DDIM, HDIM, 1><<<nsm, 256, SMEM_BYTES>>>(xa, w1h, b1, out);
    cudaStreamWaitEvent(0, evW2, 0);
    moe_gemm<HDIM, DDIM, 2><<<nsm, 256, SMEM_BYTES>>>(hbuf, w2h, b2, out);
}